// round 1
// baseline (speedup 1.0000x reference)
#include <cuda_runtime.h>
#include <cstdint>

#define NROWS 16384
#define FIN 64
#define FOUT 64
#define NP 80            // padded GEMM N: cols 0..63 = neigh_raw, col 64 = rowsum, 65..79 junk
#define MT 64            // M tile per CTA
#define KC 64            // K chunk
#define AS_STRIDE 68     // 64 + 4 pad: (68*r + t) % 32 == (4r + t) % 32 -> conflict-free frags
#define BS_STRIDE 88     // 80 + 8 pad: (88*k + c) % 32 == (24k + c) % 32 -> conflict-free frags

__device__ __align__(16) float g_B[NROWS * NP];   // [K][NP]  features|ones|0
__device__ __align__(16) float g_C[NROWS * NP];   // [M][NP]  adj @ B

// ---------------------------------------------------------------------------
// Kernel 1: build B = [features | ones | zeros]
// ---------------------------------------------------------------------------
__global__ void prep_B_kernel(const float* __restrict__ feat) {
    int idx = blockIdx.x * blockDim.x + threadIdx.x;
    const int total = NROWS * NP;
    for (; idx < total; idx += gridDim.x * blockDim.x) {
        int k = idx / NP;
        int j = idx - k * NP;
        float v = 0.0f;
        if (j < FIN) v = feat[k * FIN + j];
        else if (j == FIN) v = 1.0f;
        g_B[idx] = v;
    }
}

// ---------------------------------------------------------------------------
// Kernel 2: C[16384,80] = adj[16384,16384] @ B[16384,80]  via tf32 mma
// 256 CTAs, 256 threads (8 warps: 4 M-warps x 2 N-warps), warp tile 16x40.
// Register-prefetch double buffering over 256 K-chunks of 64.
// ---------------------------------------------------------------------------
__global__ __launch_bounds__(256, 2) void gemm_adj_kernel(const float* __restrict__ adj) {
    __shared__ float As[MT * AS_STRIDE];   // 64 x 68 fp32 = 17408 B
    __shared__ float Bs[KC * BS_STRIDE];   // 64 x 88 fp32 = 22528 B

    const int t    = threadIdx.x;
    const int warp = t >> 5;
    const int lane = t & 31;
    const int wm   = warp >> 1;        // 0..3  -> M sub-tile of 16 rows
    const int wn   = warp & 1;         // 0..1  -> N half of 40 cols
    const int g    = lane >> 2;        // groupID 0..7
    const int tg   = lane & 3;         // thread-in-group 0..3
    const int i0   = blockIdx.x * MT;

    // per-thread load coordinates (fixed across chunks)
    int ar[4], ac[4];                  // A: 1024 float4 per chunk, 4 per thread
#pragma unroll
    for (int j = 0; j < 4; ++j) {
        int idx = t + 256 * j;
        ar[j] = idx >> 4;              // row 0..63 (16 float4 per row)
        ac[j] = (idx & 15) << 2;       // col in floats
    }
    int br[5], bc[5];                  // B: 1280 float4 per chunk, 5 per thread
#pragma unroll
    for (int j = 0; j < 5; ++j) {
        int idx = t + 256 * j;
        br[j] = idx / 20;              // row 0..63 (20 float4 per row)
        bc[j] = (idx % 20) << 2;
    }

    float4 pa[4], pb[5];
    // preload chunk 0
#pragma unroll
    for (int j = 0; j < 4; ++j)
        pa[j] = *(const float4*)(adj + (size_t)(i0 + ar[j]) * NROWS + ac[j]);
#pragma unroll
    for (int j = 0; j < 5; ++j)
        pb[j] = *(const float4*)(g_B + br[j] * NP + bc[j]);

    float acc[5][4];
#pragma unroll
    for (int n = 0; n < 5; ++n)
#pragma unroll
        for (int v = 0; v < 4; ++v) acc[n][v] = 0.0f;

    const int NCHUNK = NROWS / KC;     // 256
    for (int ch = 0; ch < NCHUNK; ++ch) {
        // commit prefetched chunk to smem
#pragma unroll
        for (int j = 0; j < 4; ++j)
            *(float4*)(As + ar[j] * AS_STRIDE + ac[j]) = pa[j];
#pragma unroll
        for (int j = 0; j < 5; ++j)
            *(float4*)(Bs + br[j] * BS_STRIDE + bc[j]) = pb[j];
        __syncthreads();

        // issue next chunk's global loads (latency hidden under mma below)
        if (ch + 1 < NCHUNK) {
            const int kb = (ch + 1) * KC;
#pragma unroll
            for (int j = 0; j < 4; ++j)
                pa[j] = *(const float4*)(adj + (size_t)(i0 + ar[j]) * NROWS + kb + ac[j]);
#pragma unroll
            for (int j = 0; j < 5; ++j)
                pb[j] = *(const float4*)(g_B + (size_t)(kb + br[j]) * NP + bc[j]);
        }

        // compute: 8 k-steps of 8
        const float* abase = As + (wm * 16 + g) * AS_STRIDE + tg;
#pragma unroll
        for (int ks = 0; ks < 8; ++ks) {
            const int kk = ks * 8;
            const float* ap = abase + kk;
            uint32_t a0 = __float_as_uint(ap[0]);
            uint32_t a1 = __float_as_uint(ap[8 * AS_STRIDE]);
            uint32_t a2 = __float_as_uint(ap[4]);
            uint32_t a3 = __float_as_uint(ap[8 * AS_STRIDE + 4]);
            const float* bbase = Bs + (kk + tg) * BS_STRIDE + wn * 40 + g;
#pragma unroll
            for (int nt = 0; nt < 5; ++nt) {
                const float* bp = bbase + nt * 8;
                uint32_t b0 = __float_as_uint(bp[0]);
                uint32_t b1 = __float_as_uint(bp[4 * BS_STRIDE]);
                asm volatile(
                    "mma.sync.aligned.m16n8k8.row.col.f32.tf32.tf32.f32 "
                    "{%0,%1,%2,%3}, {%4,%5,%6,%7}, {%8,%9}, {%0,%1,%2,%3};\n"
                    : "+f"(acc[nt][0]), "+f"(acc[nt][1]),
                      "+f"(acc[nt][2]), "+f"(acc[nt][3])
                    : "r"(a0), "r"(a1), "r"(a2), "r"(a3), "r"(b0), "r"(b1));
            }
        }
        __syncthreads();
    }

    // epilogue: store raw C (division by deg happens in proj kernel)
    const int row = i0 + wm * 16 + g;
#pragma unroll
    for (int nt = 0; nt < 5; ++nt) {
        const int col = wn * 40 + nt * 8 + 2 * tg;
        *(float2*)(g_C + (size_t)row * NP + col)       = make_float2(acc[nt][0], acc[nt][1]);
        *(float2*)(g_C + (size_t)(row + 8) * NP + col) = make_float2(acc[nt][2], acc[nt][3]);
    }
}

// ---------------------------------------------------------------------------
// Kernel 3: out[i][o] = sum_j data[i][j] * W[o][j],
//           data = [features | C/(rowsum+1)], 16 rows per block.
// ---------------------------------------------------------------------------
__global__ __launch_bounds__(256) void proj_kernel(const float* __restrict__ feat,
                                                   const float* __restrict__ W,
                                                   float* __restrict__ out) {
    __shared__ float Ws[FOUT][2 * FIN + 1];   // 64 x 129 fp32 = 33024 B
    __shared__ float Ds[16][2 * FIN + 1];     // 16 x 129 fp32 =  8256 B
    __shared__ float inv[16];

    const int t  = threadIdx.x;
    const int r0 = blockIdx.x * 16;

    // load W (64 x 128) into padded smem
    for (int idx = t; idx < FOUT * 2 * FIN; idx += 256) {
        int o = idx >> 7, j = idx & 127;
        Ws[o][j] = W[idx];
    }
    if (t < 16) inv[t] = 1.0f / (g_C[(size_t)(r0 + t) * NP + FIN] + 1.0f);
    __syncthreads();

    // build data rows: [features | neigh]
    for (int idx = t; idx < 16 * 2 * FIN; idx += 256) {
        int r = idx >> 7, j = idx & 127;
        float v = (j < FIN) ? feat[(size_t)(r0 + r) * FIN + j]
                            : g_C[(size_t)(r0 + r) * NP + (j - FIN)] * inv[r];
        Ds[r][j] = v;
    }
    __syncthreads();

    const int r = t >> 4;     // 16 rows, 16 threads per row
    const int q = t & 15;     // each thread does 4 output cols
    float acc[4] = {0.0f, 0.0f, 0.0f, 0.0f};
#pragma unroll 4
    for (int j = 0; j < 2 * FIN; ++j) {
        float d = Ds[r][j];
#pragma unroll
        for (int u = 0; u < 4; ++u)
            acc[u] += d * Ws[q * 4 + u][j];
    }
#pragma unroll
    for (int u = 0; u < 4; ++u)
        out[(size_t)(r0 + r) * FOUT + q * 4 + u] = acc[u];
}

// ---------------------------------------------------------------------------
extern "C" void kernel_launch(void* const* d_in, const int* in_sizes, int n_in,
                              void* d_out, int out_size) {
    // map inputs by element count (features=1048576, adj=268435456, W=8192)
    const float* feat = nullptr;
    const float* adj  = nullptr;
    const float* W    = nullptr;
    for (int i = 0; i < n_in; ++i) {
        if (in_sizes[i] == NROWS * FIN)          feat = (const float*)d_in[i];
        else if (in_sizes[i] == FOUT * 2 * FIN)  W    = (const float*)d_in[i];
        else                                     adj  = (const float*)d_in[i];
    }

    prep_B_kernel<<<256, 256>>>(feat);
    gemm_adj_kernel<<<NROWS / MT, 256>>>(adj);
    proj_kernel<<<NROWS / 16, 256>>>(feat, W, (float*)d_out);
}

// round 3
// speedup vs baseline: 2.8413x; 2.8413x over previous
#include <cuda_runtime.h>
#include <cuda_bf16.h>
#include <cstdint>

#define NROWS 16384
#define FIN 64
#define FOUT 64
#define NP 80            // GEMM N: 0..63 = H cols, 64 = ones->rowsum, 65..79 pad
#define MT 64            // M rows per CTA
#define KC 64            // K per chunk
#define SA 72            // A smem stride in bf16 (144B: 16B shift/row -> LDSM conflict-free)
#define SB 88            // B smem stride in bf16 (176B: 48B shift/row -> LDSM conflict-free)
#define PREP_SMEM (2 * 128 * 65 * 4)

__device__ __align__(256) __nv_bfloat16 g_B[NROWS * NP];  // [k][80]: feat@W2^T | 1 | 0
__device__ __align__(256) float g_F1[NROWS * FOUT];       // feat @ W1^T

__device__ __forceinline__ uint32_t smem_u32(const void* p) {
  uint32_t a;
  asm("{ .reg .u64 t; cvta.to.shared.u64 t, %1; cvt.u32.u64 %0, t; }" : "=r"(a) : "l"(p));
  return a;
}
__device__ __forceinline__ void ldsm_x4(uint32_t* r, uint32_t a) {
  asm volatile("ldmatrix.sync.aligned.m8n8.x4.shared.b16 {%0,%1,%2,%3}, [%4];"
               : "=r"(r[0]), "=r"(r[1]), "=r"(r[2]), "=r"(r[3]) : "r"(a));
}
__device__ __forceinline__ void ldsm_x4t(uint32_t* r, uint32_t a) {
  asm volatile("ldmatrix.sync.aligned.m8n8.x4.trans.shared.b16 {%0,%1,%2,%3}, [%4];"
               : "=r"(r[0]), "=r"(r[1]), "=r"(r[2]), "=r"(r[3]) : "r"(a));
}
__device__ __forceinline__ void ldsm_x2t(uint32_t* r, uint32_t a) {
  asm volatile("ldmatrix.sync.aligned.m8n8.x2.trans.shared.b16 {%0,%1}, [%2];"
               : "=r"(r[0]), "=r"(r[1]) : "r"(a));
}
__device__ __forceinline__ void mma_bf16(float* c, const uint32_t* a, uint32_t b0, uint32_t b1) {
  asm volatile(
      "mma.sync.aligned.m16n8k16.row.col.f32.bf16.bf16.f32 "
      "{%0,%1,%2,%3}, {%4,%5,%6,%7}, {%8,%9}, {%0,%1,%2,%3};\n"
      : "+f"(c[0]), "+f"(c[1]), "+f"(c[2]), "+f"(c[3])
      : "r"(a[0]), "r"(a[1]), "r"(a[2]), "r"(a[3]), "r"(b0), "r"(b1));
}

// ---------------------------------------------------------------------------
// prep: g_F1 = feat@W1^T (f32); g_B[k][0..63] = (feat@W2^T) bf16; col64=1; 65..79=0
// ---------------------------------------------------------------------------
__global__ __launch_bounds__(256, 1) void prep_kernel(const float* __restrict__ feat,
                                                      const float* __restrict__ W) {
  extern __shared__ float sm[];
  float* Fs = sm;             // [128][65]
  float* Ws = sm + 128 * 65;  // rows 0..63 = W1, rows 64..127 = W2 (col-padded 65)
  const int tid = threadIdx.x;
  const int k0 = blockIdx.x * 128;

  for (int idx = tid; idx < 128 * 64; idx += 256) {
    int r = idx >> 6, j = idx & 63;
    Fs[r * 65 + j] = feat[(size_t)(k0 + r) * 64 + j];
  }
  for (int idx = tid; idx < 64 * 128; idx += 256) {
    int o = idx >> 7, j = idx & 127;
    Ws[((j < 64) ? o : 64 + o) * 65 + (j & 63)] = W[idx];
  }
  __syncthreads();

  const int r = tid & 127;
  const int half = tid >> 7;
  float acc[64];
#pragma unroll
  for (int o = 0; o < 64; ++o) acc[o] = 0.0f;
  const float* wbase = Ws + half * 64 * 65;
#pragma unroll 4
  for (int j = 0; j < 64; ++j) {
    float f = Fs[r * 65 + j];
#pragma unroll
    for (int o = 0; o < 64; ++o) acc[o] += f * wbase[o * 65 + j];
  }
  if (half == 0) {
    float4* dst = (float4*)(g_F1 + (size_t)(k0 + r) * 64);
#pragma unroll
    for (int q = 0; q < 16; ++q)
      dst[q] = make_float4(acc[4 * q], acc[4 * q + 1], acc[4 * q + 2], acc[4 * q + 3]);
  } else {
    __nv_bfloat162* dst = (__nv_bfloat162*)(g_B + (size_t)(k0 + r) * NP);
#pragma unroll
    for (int o = 0; o < 32; ++o)
      dst[o] = __floats2bfloat162_rn(acc[2 * o], acc[2 * o + 1]);
  }
  // pad cols 64..79
  for (int idx = tid; idx < 128 * 16; idx += 256) {
    int rr = idx >> 4, c = 64 + (idx & 15);
    g_B[(size_t)(k0 + rr) * NP + c] = __float2bfloat16((c == 64) ? 1.0f : 0.0f);
  }
}

// ---------------------------------------------------------------------------
// gemm: C[64,80] = adj_tile(f32->bf16) @ g_B ; out = g_F1 + C[:,:64]/(C[:,64]+1)
// 8 warps = 4 m-warps (16 rows) x 2 n-warps (40 cols). bf16 m16n8k16 + ldmatrix.
// ---------------------------------------------------------------------------
__global__ __launch_bounds__(256, 2) void gemm_kernel(const float* __restrict__ adj,
                                                      float* __restrict__ out) {
  __shared__ __nv_bfloat16 As[MT * SA];   // 9216 B
  __shared__ __nv_bfloat16 Bs[KC * SB];   // 11264 B
  __shared__ float rs[MT];

  const int tid = threadIdx.x;
  const int warp = tid >> 5;
  const int lane = tid & 31;
  const int wm = warp >> 1;  // 0..3
  const int wn = warp & 1;   // 0..1
  const int i0 = blockIdx.x * MT;

  // ---- global load coords (fixed across chunks) ----
  int ar[4], ac4[4];  // A: 64x64 f32 = 1024 float4, 4/thread
#pragma unroll
  for (int j = 0; j < 4; ++j) {
    int idx = tid + 256 * j;
    ar[j] = idx >> 4;
    ac4[j] = idx & 15;
  }
  int br[3], bc[3];   // B: 64 rows x 10 uint4 = 640, <=3/thread
#pragma unroll
  for (int j = 0; j < 3; ++j) {
    int idx = tid + 256 * j;
    br[j] = idx / 10;
    bc[j] = idx % 10;
  }
  const bool bok2 = (tid + 512) < 640;

  // ---- ldmatrix lane addresses ----
  const uint32_t a_base = smem_u32(As);
  const uint32_t b_base = smem_u32(Bs);
  const int aRow = wm * 16 + (lane & 7) + ((lane >> 3) & 1) * 8;
  const uint32_t aAddr0 = a_base + (uint32_t)(aRow * SA + (lane >> 4) * 8) * 2;
  const int bRow = (lane & 7) + ((lane >> 3) & 1) * 8;
  const int nOff = (lane >> 4) * 8;
  const uint32_t bAddrP0 = b_base + (uint32_t)(bRow * SB + wn * 40 + nOff) * 2;
  const uint32_t bAddrP1 = bAddrP0 + 16 * 2;
  const uint32_t bAddr4 = b_base + (uint32_t)(bRow * SB + wn * 40 + 32) * 2;

  // ---- prefetch chunk 0 ----
  float4 pa[4];
  uint4 pb[3];
#pragma unroll
  for (int j = 0; j < 4; ++j)
    pa[j] = *(const float4*)(adj + (size_t)(i0 + ar[j]) * NROWS + ac4[j] * 4);
#pragma unroll
  for (int j = 0; j < 2; ++j)
    pb[j] = *(const uint4*)(g_B + (size_t)br[j] * NP + bc[j] * 8);
  if (bok2) pb[2] = *(const uint4*)(g_B + (size_t)br[2] * NP + bc[2] * 8);

  float acc[5][4];
#pragma unroll
  for (int n = 0; n < 5; ++n)
#pragma unroll
    for (int v = 0; v < 4; ++v) acc[n][v] = 0.0f;

  const int NCHUNK = NROWS / KC;  // 256
  for (int ch = 0; ch < NCHUNK; ++ch) {
    // commit to smem (A converted f32->bf16)
#pragma unroll
    for (int j = 0; j < 4; ++j) {
      __nv_bfloat162 lo = __floats2bfloat162_rn(pa[j].x, pa[j].y);
      __nv_bfloat162 hi = __floats2bfloat162_rn(pa[j].z, pa[j].w);
      uint32_t* d = (uint32_t*)(As + ar[j] * SA + ac4[j] * 4);
      d[0] = *(uint32_t*)&lo;
      d[1] = *(uint32_t*)&hi;
    }
#pragma unroll
    for (int j = 0; j < 2; ++j)
      *(uint4*)(Bs + br[j] * SB + bc[j] * 8) = pb[j];
    if (bok2) *(uint4*)(Bs + br[2] * SB + bc[2] * 8) = pb[2];
    __syncthreads();

    // prefetch next chunk
    if (ch + 1 < NCHUNK) {
      const size_t kb = (size_t)(ch + 1) * KC;
#pragma unroll
      for (int j = 0; j < 4; ++j)
        pa[j] = *(const float4*)(adj + (size_t)(i0 + ar[j]) * NROWS + kb + ac4[j] * 4);
#pragma unroll
      for (int j = 0; j < 2; ++j)
        pb[j] = *(const uint4*)(g_B + (kb + br[j]) * NP + bc[j] * 8);
      if (bok2) pb[2] = *(const uint4*)(g_B + (kb + br[2]) * NP + bc[2] * 8);
    }

    // compute: 4 k16 steps
#pragma unroll
    for (int ks = 0; ks < 4; ++ks) {
      uint32_t a[4], b01[4], b23[4], b4[2];
      ldsm_x4(a, aAddr0 + (uint32_t)(ks * 16 * 2));
      const uint32_t brow = (uint32_t)(ks * 16 * SB * 2);
      ldsm_x4t(b01, bAddrP0 + brow);
      ldsm_x4t(b23, bAddrP1 + brow);
      ldsm_x2t(b4, bAddr4 + brow);
      mma_bf16(acc[0], a, b01[0], b01[1]);
      mma_bf16(acc[1], a, b01[2], b01[3]);
      mma_bf16(acc[2], a, b23[0], b23[1]);
      mma_bf16(acc[3], a, b23[2], b23[3]);
      mma_bf16(acc[4], a, b4[0], b4[1]);
    }
    __syncthreads();
  }

  // ---- epilogue ----
  // rowsum = col 64 = wn1 tile 3 col-offset 0 -> threads (lane&3)==0
  if (wn == 1 && (lane & 3) == 0) {
    rs[wm * 16 + (lane >> 2)] = acc[3][0];
    rs[wm * 16 + (lane >> 2) + 8] = acc[3][2];
  }
  __syncthreads();

  const int rl0 = wm * 16 + (lane >> 2);
  const int rl1 = rl0 + 8;
  const float inv0 = 1.0f / (rs[rl0] + 1.0f);
  const float inv1 = 1.0f / (rs[rl1] + 1.0f);
  const int ntMax = (wn == 0) ? 5 : 3;
#pragma unroll
  for (int nt = 0; nt < 5; ++nt) {
    if (nt >= ntMax) break;
    const int col = wn * 40 + nt * 8 + 2 * (lane & 3);
    const float2 f0 = *(const float2*)(g_F1 + (size_t)(i0 + rl0) * 64 + col);
    const float2 f1 = *(const float2*)(g_F1 + (size_t)(i0 + rl1) * 64 + col);
    *(float2*)(out + (size_t)(i0 + rl0) * 64 + col) =
        make_float2(f0.x + acc[nt][0] * inv0, f0.y + acc[nt][1] * inv0);
    *(float2*)(out + (size_t)(i0 + rl1) * 64 + col) =
        make_float2(f1.x + acc[nt][2] * inv1, f1.y + acc[nt][3] * inv1);
  }
}

// ---------------------------------------------------------------------------
extern "C" void kernel_launch(void* const* d_in, const int* in_sizes, int n_in,
                              void* d_out, int out_size) {
  const float* feat = nullptr;
  const float* adj = nullptr;
  const float* W = nullptr;
  for (int i = 0; i < n_in; ++i) {
    if (in_sizes[i] == NROWS * FIN)          feat = (const float*)d_in[i];
    else if (in_sizes[i] == FOUT * 2 * FIN)  W    = (const float*)d_in[i];
    else                                     adj  = (const float*)d_in[i];
  }

  cudaFuncSetAttribute(prep_kernel, cudaFuncAttributeMaxDynamicSharedMemorySize, PREP_SMEM);
  prep_kernel<<<NROWS / 128, 256, PREP_SMEM>>>(feat, W);
  gemm_kernel<<<NROWS / MT, 256>>>(adj, (float*)d_out);
}

// round 4
// speedup vs baseline: 2.9876x; 1.0515x over previous
#include <cuda_runtime.h>
#include <cuda_bf16.h>
#include <cstdint>

#define NROWS 16384
#define FIN 64
#define FOUT 64
#define NP 80            // g_B row: 0..63 = feat@W2^T, 64 = ones, 65..79 = 0
#define NC 72            // stored C cols (64 + rowsum + 7 pad)
#define MT 128           // M rows per CTA
#define KC 32            // K per chunk
#define KHALF (NROWS / 2)
#define NCHUNK (KHALF / KC)   // 256
#define SA 40            // A smem stride (bf16): 80B/row -> LDSM conflict-free
#define SB 88            // B smem stride (bf16): 176B/row -> LDSM conflict-free
#define PREP_SMEM (2 * 128 * 65 * 4)

__device__ __align__(256) __nv_bfloat16 g_B[NROWS * NP];
__device__ __align__(256) float g_F1[NROWS * FOUT];
__device__ __align__(256) float g_Cp[2][NROWS * NC];   // k-half partials

__device__ __forceinline__ uint32_t smem_u32(const void* p) {
  uint32_t a;
  asm("{ .reg .u64 t; cvta.to.shared.u64 t, %1; cvt.u32.u64 %0, t; }" : "=r"(a) : "l"(p));
  return a;
}
__device__ __forceinline__ void ldsm_x4(uint32_t* r, uint32_t a) {
  asm volatile("ldmatrix.sync.aligned.m8n8.x4.shared.b16 {%0,%1,%2,%3}, [%4];"
               : "=r"(r[0]), "=r"(r[1]), "=r"(r[2]), "=r"(r[3]) : "r"(a));
}
__device__ __forceinline__ void ldsm_x4t(uint32_t* r, uint32_t a) {
  asm volatile("ldmatrix.sync.aligned.m8n8.x4.trans.shared.b16 {%0,%1,%2,%3}, [%4];"
               : "=r"(r[0]), "=r"(r[1]), "=r"(r[2]), "=r"(r[3]) : "r"(a));
}
__device__ __forceinline__ void ldsm_x2t(uint32_t* r, uint32_t a) {
  asm volatile("ldmatrix.sync.aligned.m8n8.x2.trans.shared.b16 {%0,%1}, [%2];"
               : "=r"(r[0]), "=r"(r[1]) : "r"(a));
}
__device__ __forceinline__ void mma_bf16(float* c, const uint32_t* a, uint32_t b0, uint32_t b1) {
  asm volatile(
      "mma.sync.aligned.m16n8k16.row.col.f32.bf16.bf16.f32 "
      "{%0,%1,%2,%3}, {%4,%5,%6,%7}, {%8,%9}, {%0,%1,%2,%3};\n"
      : "+f"(c[0]), "+f"(c[1]), "+f"(c[2]), "+f"(c[3])
      : "r"(a[0]), "r"(a[1]), "r"(a[2]), "r"(a[3]), "r"(b0), "r"(b1));
}

// ---------------------------------------------------------------------------
// prep: g_F1 = feat@W1^T (f32); g_B[k][0..63] = feat@W2^T (bf16); 64=1; 65..79=0
// ---------------------------------------------------------------------------
__global__ __launch_bounds__(256, 1) void prep_kernel(const float* __restrict__ feat,
                                                      const float* __restrict__ W) {
  extern __shared__ float sm[];
  float* Fs = sm;             // [128][65]
  float* Ws = sm + 128 * 65;  // rows 0..63 = W1, 64..127 = W2
  const int tid = threadIdx.x;
  const int k0 = blockIdx.x * 128;

  for (int idx = tid; idx < 128 * 64; idx += 256) {
    int r = idx >> 6, j = idx & 63;
    Fs[r * 65 + j] = feat[(size_t)(k0 + r) * 64 + j];
  }
  for (int idx = tid; idx < 64 * 128; idx += 256) {
    int o = idx >> 7, j = idx & 127;
    Ws[((j < 64) ? o : 64 + o) * 65 + (j & 63)] = W[idx];
  }
  __syncthreads();

  const int r = tid & 127;
  const int half = tid >> 7;
  float acc[64];
#pragma unroll
  for (int o = 0; o < 64; ++o) acc[o] = 0.0f;
  const float* wbase = Ws + half * 64 * 65;
#pragma unroll 4
  for (int j = 0; j < 64; ++j) {
    float f = Fs[r * 65 + j];
#pragma unroll
    for (int o = 0; o < 64; ++o) acc[o] += f * wbase[o * 65 + j];
  }
  if (half == 0) {
    float4* dst = (float4*)(g_F1 + (size_t)(k0 + r) * 64);
#pragma unroll
    for (int q = 0; q < 16; ++q)
      dst[q] = make_float4(acc[4 * q], acc[4 * q + 1], acc[4 * q + 2], acc[4 * q + 3]);
  } else {
    __nv_bfloat162* dst = (__nv_bfloat162*)(g_B + (size_t)(k0 + r) * NP);
#pragma unroll
    for (int o = 0; o < 32; ++o)
      dst[o] = __floats2bfloat162_rn(acc[2 * o], acc[2 * o + 1]);
  }
  for (int idx = tid; idx < 128 * 16; idx += 256) {
    int rr = idx >> 4, c = 64 + (idx & 15);
    g_B[(size_t)(k0 + rr) * NP + c] = __float2bfloat16((c == 64) ? 1.0f : 0.0f);
  }
}

// ---------------------------------------------------------------------------
// gemm: Cp[kh][128-row block] = adj(rows, k-half) @ g_B(k-half)
// 8 warps = 4m(32 rows) x 2n(40 cols); wn=1 skips pad tile (cols 72..79).
// ---------------------------------------------------------------------------
__global__ __launch_bounds__(256, 2) void gemm_kernel(const float* __restrict__ adj) {
  __shared__ __nv_bfloat16 As[MT * SA];   // 10240 B
  __shared__ __nv_bfloat16 Bs[KC * SB];   //  5632 B

  const int tid = threadIdx.x;
  const int warp = tid >> 5;
  const int lane = tid & 31;
  const int wm = warp >> 1;        // 0..3 -> 32-row slice
  const int wn = warp & 1;         // 0..1 -> 40-col half
  const int rowBlk = blockIdx.x >> 1;
  const int kh = blockIdx.x & 1;
  const int i0 = rowBlk * MT;
  const size_t kbase0 = (size_t)kh * KHALF;

  // ---- global load coords ----
  int ar[4], ac4[4];   // A: 128x32 f32 = 1024 float4, 4/thread (8 per row)
#pragma unroll
  for (int j = 0; j < 4; ++j) {
    int idx = tid + 256 * j;
    ar[j] = idx >> 3;
    ac4[j] = idx & 7;
  }
  // B: 32 rows x 10 uint4 = 320; thread -> idx tid and (tid<64) idx 256+tid
  const int br0 = tid / 10, bc0 = tid % 10;
  const int br1 = (tid + 256) / 10, bc1 = (tid + 256) % 10;
  const bool bok1 = tid < 64;

  // ---- ldmatrix lane addresses ----
  const uint32_t a_base = smem_u32(As);
  const uint32_t b_base = smem_u32(Bs);
  const uint32_t aAddr = a_base +
      (uint32_t)((wm * 32 + (lane & 15)) * SA + (lane >> 4) * 8) * 2;
  const int bRow = lane & 15;
  const int nOff = (lane >> 4) * 8;
  const uint32_t bAddrP0 = b_base + (uint32_t)(bRow * SB + wn * 40 + nOff) * 2;
  const uint32_t bAddrP1 = bAddrP0 + 16 * 2;
  const uint32_t bAddr4 = b_base + (uint32_t)(bRow * SB + 32 + nOff) * 2;  // wn0 only (x2t uses lanes 0..15)

  // ---- prefetch chunk 0 ----
  float4 pa[4];
  uint4 pb0, pb1;
#pragma unroll
  for (int j = 0; j < 4; ++j)
    pa[j] = *(const float4*)(adj + (size_t)(i0 + ar[j]) * NROWS + kbase0 + ac4[j] * 4);
  pb0 = *(const uint4*)(g_B + (kbase0 + br0) * NP + bc0 * 8);
  if (bok1) pb1 = *(const uint4*)(g_B + (kbase0 + br1) * NP + bc1 * 8);

  float acc[2][5][4];
#pragma unroll
  for (int m = 0; m < 2; ++m)
#pragma unroll
    for (int n = 0; n < 5; ++n)
#pragma unroll
      for (int v = 0; v < 4; ++v) acc[m][n][v] = 0.0f;

  for (int ch = 0; ch < NCHUNK; ++ch) {
    // commit prefetched chunk (A f32->bf16)
#pragma unroll
    for (int j = 0; j < 4; ++j) {
      __nv_bfloat162 lo = __floats2bfloat162_rn(pa[j].x, pa[j].y);
      __nv_bfloat162 hi = __floats2bfloat162_rn(pa[j].z, pa[j].w);
      uint32_t* d = (uint32_t*)(As + ar[j] * SA + ac4[j] * 4);
      d[0] = *(uint32_t*)&lo;
      d[1] = *(uint32_t*)&hi;
    }
    *(uint4*)(Bs + br0 * SB + bc0 * 8) = pb0;
    if (bok1) *(uint4*)(Bs + br1 * SB + bc1 * 8) = pb1;
    __syncthreads();

    // prefetch next chunk
    if (ch + 1 < NCHUNK) {
      const size_t kb = kbase0 + (size_t)(ch + 1) * KC;
#pragma unroll
      for (int j = 0; j < 4; ++j)
        pa[j] = *(const float4*)(adj + (size_t)(i0 + ar[j]) * NROWS + kb + ac4[j] * 4);
      pb0 = *(const uint4*)(g_B + (kb + br0) * NP + bc0 * 8);
      if (bok1) pb1 = *(const uint4*)(g_B + (kb + br1) * NP + bc1 * 8);
    }

    // compute: 2 k16 steps
#pragma unroll
    for (int ks = 0; ks < 2; ++ks) {
      uint32_t a0[4], a1[4], b01[4], b23[4], b4[2];
      const uint32_t ko = (uint32_t)(ks * 16 * 2);
      const uint32_t bo = (uint32_t)(ks * 16 * SB * 2);
      ldsm_x4(a0, aAddr + ko);
      ldsm_x4(a1, aAddr + (uint32_t)(16 * SA * 2) + ko);
      ldsm_x4t(b01, bAddrP0 + bo);
      ldsm_x4t(b23, bAddrP1 + bo);
      if (wn == 0) {
        ldsm_x2t(b4, bAddr4 + bo);
        mma_bf16(acc[0][4], a0, b4[0], b4[1]);
        mma_bf16(acc[1][4], a1, b4[0], b4[1]);
      }
      mma_bf16(acc[0][0], a0, b01[0], b01[1]);
      mma_bf16(acc[0][1], a0, b01[2], b01[3]);
      mma_bf16(acc[0][2], a0, b23[0], b23[1]);
      mma_bf16(acc[0][3], a0, b23[2], b23[3]);
      mma_bf16(acc[1][0], a1, b01[0], b01[1]);
      mma_bf16(acc[1][1], a1, b01[2], b01[3]);
      mma_bf16(acc[1][2], a1, b23[0], b23[1]);
      mma_bf16(acc[1][3], a1, b23[2], b23[3]);
    }
    __syncthreads();
  }

  // ---- store partial C ----
  float* Cp = g_Cp[kh];
  const int ntMax = (wn == 0) ? 5 : 4;
#pragma unroll
  for (int m = 0; m < 2; ++m) {
    const int r0 = i0 + wm * 32 + 16 * m + (lane >> 2);
#pragma unroll
    for (int nt = 0; nt < 5; ++nt) {
      if (nt >= ntMax) break;
      const int col = wn * 40 + nt * 8 + 2 * (lane & 3);
      *(float2*)(Cp + (size_t)r0 * NC + col) = make_float2(acc[m][nt][0], acc[m][nt][1]);
      *(float2*)(Cp + (size_t)(r0 + 8) * NC + col) = make_float2(acc[m][nt][2], acc[m][nt][3]);
    }
  }
}

// ---------------------------------------------------------------------------
// epi: out = F1 + (C0 + C1)[:, :64] / (C0[:,64] + C1[:,64] + 1)
// ---------------------------------------------------------------------------
__global__ __launch_bounds__(256, 4) void epi_kernel(float* __restrict__ out) {
  __shared__ float inv[32];
  const int tid = threadIdx.x;
  const int r0 = blockIdx.x * 32;

  if (tid < 32)
    inv[tid] = 1.0f / (g_Cp[0][(size_t)(r0 + tid) * NC + 64] +
                       g_Cp[1][(size_t)(r0 + tid) * NC + 64] + 1.0f);
  __syncthreads();

  const int r = tid >> 3;
  const int c = (tid & 7) * 8;
  const int row = r0 + r;
  const float iv = inv[r];
  const size_t cb = (size_t)row * NC + c;
  const size_t fb = (size_t)row * 64 + c;
#pragma unroll
  for (int h = 0; h < 2; ++h) {
    float4 c0 = *(const float4*)(g_Cp[0] + cb + 4 * h);
    float4 c1 = *(const float4*)(g_Cp[1] + cb + 4 * h);
    float4 f = *(const float4*)(g_F1 + fb + 4 * h);
    *(float4*)(out + fb + 4 * h) =
        make_float4(f.x + (c0.x + c1.x) * iv, f.y + (c0.y + c1.y) * iv,
                    f.z + (c0.z + c1.z) * iv, f.w + (c0.w + c1.w) * iv);
  }
}

// ---------------------------------------------------------------------------
extern "C" void kernel_launch(void* const* d_in, const int* in_sizes, int n_in,
                              void* d_out, int out_size) {
  const float* feat = nullptr;
  const float* adj = nullptr;
  const float* W = nullptr;
  for (int i = 0; i < n_in; ++i) {
    if (in_sizes[i] == NROWS * FIN)          feat = (const float*)d_in[i];
    else if (in_sizes[i] == FOUT * 2 * FIN)  W    = (const float*)d_in[i];
    else                                     adj  = (const float*)d_in[i];
  }

  cudaFuncSetAttribute(prep_kernel, cudaFuncAttributeMaxDynamicSharedMemorySize, PREP_SMEM);
  prep_kernel<<<NROWS / 128, 256, PREP_SMEM>>>(feat, W);
  gemm_kernel<<<2 * (NROWS / MT), 256>>>(adj);
  epi_kernel<<<NROWS / 32, 256>>>((float*)d_out);
}